// round 17
// baseline (speedup 1.0000x reference)
#include <cuda_runtime.h>
#include <cuda_bf16.h>
#include <stdint.h>
#include <math.h>

// ---------------------------------------------------------------- constants
#define IN_DIM   1024
#define OUT_DIM  1024
#define L_DIM    4096
#define B_DIM    1024
#define NCOLS    3072
#define NSTEPS   32
#define EPS_N    1e-12f

// GEMM: C(M=1024, N=3072). CTA 128x192, K-chunk 64.
#define MT       128
#define NT       192
#define KC       64
#define NKC      64            // total K chunks in act layout
#define NITER    48            // per-step chunks: 32 hid + 16 out (x hoisted)
#define MTILES   8
#define NTILES   16            // grid 16x8 = 128 CTAs (one wave)

#define ROWB     128           // bytes per row (64 bf16) - SW128 atom
#define ABLK     (MT*ROWB)     // 16384
#define BBLK     (NT*ROWB)     // 24576
#define STAGE    (2*ABLK + 2*BBLK)   // 81920
#define NSTG     2
#define SMEM_DATA (NSTG*STAGE)       // 163840
#define SM_MBAR   SMEM_DATA
#define SM_SSCALE (SMEM_DATA + 64)
#define SM_SPART  (SMEM_DATA + 64 + 512)
#define SMEM_TOT  (SMEM_DATA + 64 + 512 + 2048)

#define ACT_BUF  ((size_t)MTILES * NKC * ABLK)   // 8 MB per buffer
#define WT_TOT   ((size_t)NTILES * NKC * BBLK)   // 24 MB

// hid cols are n >= 1024 -> ntiles 5..15 contribute
#define PART_T0  5
#define NPART    11

// ---------------------------------------------------------------- device scratch
__device__ __align__(1024) char g_wt_hi[WT_TOT];
__device__ __align__(1024) char g_wt_lo[WT_TOT];
__device__ __align__(1024) char g_act_hi[2 * ACT_BUF];
__device__ __align__(1024) char g_act_lo[2 * ACT_BUF];
__device__ float g_part[NPART][B_DIM];                 // hid sum-of-squares partials
__device__ __align__(1024) float g_cx[(size_t)B_DIM * NCOLS];   // 12 MB: x @ mw_x^T

// ---------------------------------------------------------------- helpers
__device__ __forceinline__ uint32_t swz128(uint32_t b) { return b ^ ((b >> 3) & 0x70u); }

__device__ __forceinline__ uint32_t s2u(const void* p) {
    uint32_t a;
    asm("{ .reg .u64 t; cvta.to.shared.u64 t, %1; cvt.u32.u64 %0, t; }" : "=r"(a) : "l"(p));
    return a;
}
__device__ __forceinline__ void mbar_init(uint32_t a, uint32_t c) {
    asm volatile("mbarrier.init.shared.b64 [%0], %1;" :: "r"(a), "r"(c) : "memory");
}
__device__ __forceinline__ void mbar_expect_tx(uint32_t a, uint32_t bytes) {
    asm volatile("mbarrier.arrive.expect_tx.shared.b64 _, [%0], %1;" :: "r"(a), "r"(bytes) : "memory");
}
__device__ __forceinline__ void mbar_arrive(uint32_t a) {
    asm volatile("mbarrier.arrive.shared.b64 _, [%0];" :: "r"(a) : "memory");
}
__device__ __forceinline__ void mbar_wait(uint32_t a, uint32_t par) {
    asm volatile("{\n\t.reg .pred P;\n\tWL_%=:\n\t"
                 "mbarrier.try_wait.parity.acquire.cta.shared::cta.b64 P, [%0], %1, 0x989680;\n\t"
                 "@P bra.uni WD_%=;\n\tbra.uni WL_%=;\n\tWD_%=:\n\t}"
                 :: "r"(a), "r"(par) : "memory");
}
__device__ __forceinline__ void bulk_g2s(uint32_t dst, const void* src, uint32_t bytes, uint32_t mbar) {
    asm volatile("cp.async.bulk.shared::cluster.global.mbarrier::complete_tx::bytes [%0], [%1], %2, [%3];"
                 :: "r"(dst), "l"(src), "r"(bytes), "r"(mbar) : "memory");
}
__device__ __forceinline__ void ldsm4(uint32_t* r, uint32_t addr) {
    asm volatile("ldmatrix.sync.aligned.m8n8.x4.shared.b16 {%0,%1,%2,%3}, [%4];"
                 : "=r"(r[0]), "=r"(r[1]), "=r"(r[2]), "=r"(r[3]) : "r"(addr));
}
__device__ __forceinline__ void mma16816(float* c, const uint32_t* a, const uint32_t* b) {
    asm volatile("mma.sync.aligned.m16n8k16.row.col.f32.bf16.bf16.f32 "
                 "{%0,%1,%2,%3}, {%4,%5,%6,%7}, {%8,%9}, {%0,%1,%2,%3};"
                 : "+f"(c[0]), "+f"(c[1]), "+f"(c[2]), "+f"(c[3])
                 : "r"(a[0]), "r"(a[1]), "r"(a[2]), "r"(a[3]), "r"(b[0]), "r"(b[1]));
}

__device__ __forceinline__ void split2(float f0, float f1, uint32_t& H, uint32_t& L) {
    __nv_bfloat16 h0 = __float2bfloat16_rn(f0);
    __nv_bfloat16 h1 = __float2bfloat16_rn(f1);
    __nv_bfloat16 l0 = __float2bfloat16_rn(f0 - __bfloat162float(h0));
    __nv_bfloat16 l1 = __float2bfloat16_rn(f1 - __bfloat162float(h1));
    H = (uint32_t)__bfloat16_as_ushort(h0) | ((uint32_t)__bfloat16_as_ushort(h1) << 16);
    L = (uint32_t)__bfloat16_as_ushort(l0) | ((uint32_t)__bfloat16_as_ushort(l1) << 16);
}
__device__ __forceinline__ void split8(const float* f, uint4& H, uint4& L) {
    uint32_t hw[4], lw[4];
    #pragma unroll
    for (int p = 0; p < 4; p++) split2(f[2*p], f[2*p+1], hw[p], lw[p]);
    H = make_uint4(hw[0], hw[1], hw[2], hw[3]);
    L = make_uint4(lw[0], lw[1], lw[2], lw[3]);
}

// act tiled address: global row (0..1023), act k-index (0..4095)
__device__ __forceinline__ size_t act_off(int row, int k) {
    int mtile = row >> 7, rin = row & 127;
    int chunk = k >> 6,  cc = k & 63;
    return (size_t)(mtile * NKC + chunk) * ABLK + swz128((uint32_t)(rin * ROWB + cc * 2));
}

// ---------------------------------------------------------------- prep weights
__global__ void prep_w(const float* __restrict__ W, const float* __restrict__ A) {
    __shared__ float tile[32][33];
    const int i0 = blockIdx.y * 32, j0 = blockIdx.x * 32;
    const int tx = threadIdx.x, ty = threadIdx.y;
    tile[ty][tx] = A[(size_t)(j0 + ty) * L_DIM + (IN_DIM + i0 + tx)];
    __syncthreads();
    const int i = i0 + ty, j = j0 + tx;
    float v = W[(size_t)(IN_DIM + i) * L_DIM + j] * tile[tx][ty];
    __nv_bfloat16 h = __float2bfloat16_rn(v);
    __nv_bfloat16 l = __float2bfloat16_rn(v - __bfloat162float(h));
    const int ntile = i / NT, r = i % NT;
    const int chunk = j >> 6, cc = j & 63;
    size_t off = (size_t)(ntile * NKC + chunk) * BBLK + swz128((uint32_t)(r * ROWB + cc * 2));
    *(__nv_bfloat16*)(g_wt_hi + off) = h;
    *(__nv_bfloat16*)(g_wt_lo + off) = l;
}

// ---------------------------------------------------------------- init activations
__global__ void init_act(const float* __restrict__ x, float* __restrict__ dout) {
    int g = blockIdx.x * blockDim.x + threadIdx.x;
    if (g < NPART * B_DIM) ((float*)g_part)[g] = 0.0f;
    int row = g >> 9;
    int k0 = (g & 511) * 8;
    size_t off = act_off(row, k0);
    if (k0 < IN_DIM) {
        float4 a = *(const float4*)(x + (size_t)row * IN_DIM + k0);
        float4 b = *(const float4*)(x + (size_t)row * IN_DIM + k0 + 4);
        *(float4*)(dout + (size_t)row * L_DIM + k0)     = a;
        *(float4*)(dout + (size_t)row * L_DIM + k0 + 4) = b;
        float f[8] = {a.x, a.y, a.z, a.w, b.x, b.y, b.z, b.w};
        uint4 H, L;
        split8(f, H, L);
        *(uint4*)(g_act_hi + off) = H;
        *(uint4*)(g_act_lo + off) = L;
        *(uint4*)(g_act_hi + ACT_BUF + off) = H;
        *(uint4*)(g_act_lo + ACT_BUF + off) = L;
    } else {
        uint4 z = make_uint4(0, 0, 0, 0);
        *(uint4*)(g_act_hi + off) = z;
        *(uint4*)(g_act_lo + off) = z;
    }
}

// ---------------------------------------------------------------- old-style GEMM pieces (gemm_cx)
struct FragOffs { uint32_t a[4][4]; uint32_t b[3][4]; };

__device__ __forceinline__ void make_offs(FragOffs& o, int m0, int n0, int lane) {
    #pragma unroll
    for (int mi = 0; mi < 4; mi++)
        #pragma unroll
        for (int ks = 0; ks < 4; ks++) {
            int row = m0 + mi * 16 + (lane & 15);
            int col = ks * 32 + (lane >> 4) * 16;
            o.a[mi][ks] = swz128((uint32_t)(row * ROWB + col));
        }
    #pragma unroll
    for (int nb = 0; nb < 3; nb++)
        #pragma unroll
        for (int ks = 0; ks < 4; ks++) {
            int grp = lane >> 3;
            int row = n0 + nb * 16 + ((grp & 2) << 2) + (lane & 7);
            int col = ks * 32 + (grp & 1) * 16;
            o.b[nb][ks] = swz128((uint32_t)(row * ROWB + col));
        }
}

__device__ __forceinline__ void chunk_mma(float acc[4][6][4], const FragOffs& o,
                                          uint32_t aHiB, uint32_t aLoB,
                                          uint32_t bHiB, uint32_t bLoB) {
    #pragma unroll
    for (int ks = 0; ks < 4; ks++) {
        uint32_t ah[4][4], al[4][4], bh[6][2], bl[6][2];
        #pragma unroll
        for (int mi = 0; mi < 4; mi++) {
            ldsm4(ah[mi], aHiB + o.a[mi][ks]);
            ldsm4(al[mi], aLoB + o.a[mi][ks]);
        }
        #pragma unroll
        for (int nb = 0; nb < 3; nb++) {
            uint32_t t[4];
            ldsm4(t, bHiB + o.b[nb][ks]);
            bh[2*nb][0] = t[0]; bh[2*nb][1] = t[1];
            bh[2*nb+1][0] = t[2]; bh[2*nb+1][1] = t[3];
            ldsm4(t, bLoB + o.b[nb][ks]);
            bl[2*nb][0] = t[0]; bl[2*nb][1] = t[1];
            bl[2*nb+1][0] = t[2]; bl[2*nb+1][1] = t[3];
        }
        #pragma unroll
        for (int mi = 0; mi < 4; mi++)
            #pragma unroll
            for (int ni = 0; ni < 6; ni++) {
                mma16816(acc[mi][ni], ah[mi], bh[ni]);
                mma16816(acc[mi][ni], ah[mi], bl[ni]);
                mma16816(acc[mi][ni], al[mi], bh[ni]);
            }
    }
}

// ---------------------------------------------------------------- C_x precompute
__global__ __launch_bounds__(288, 1)
void gemm_cx(int dummy) {
    extern __shared__ __align__(1024) char smem[];
    const uint32_t sb = s2u(smem);
    const int tid = threadIdx.x, warp = tid >> 5, lane = tid & 31;
    const int ntile = blockIdx.x, mtile = blockIdx.y;

    const char* srcAh = g_act_hi + (size_t)mtile * NKC * ABLK;
    const char* srcAl = g_act_lo + (size_t)mtile * NKC * ABLK;
    const char* srcBh = g_wt_hi + (size_t)ntile * NKC * BBLK;
    const char* srcBl = g_wt_lo + (size_t)ntile * NKC * BBLK;

    const uint32_t mbF = sb + SM_MBAR;
    const uint32_t mbE = sb + SM_MBAR + 16;
    if (tid == 0) {
        mbar_init(mbF, 1); mbar_init(mbF + 8, 1);
        mbar_init(mbE, 8); mbar_init(mbE + 8, 8);
    }
    __syncthreads();

    if (warp == 8) {
        if (lane == 0) {
            for (int c = 0; c < 16; c++) {
                const int st = c & 1;
                if (c >= NSTG) mbar_wait(mbE + 8 * st, (uint32_t)(((c >> 1) - 1) & 1));
                uint32_t stB = sb + st * STAGE;
                mbar_expect_tx(mbF + 8 * st, STAGE);
                bulk_g2s(stB,                   srcAh + (size_t)c * ABLK, ABLK, mbF + 8 * st);
                bulk_g2s(stB + ABLK,            srcAl + (size_t)c * ABLK, ABLK, mbF + 8 * st);
                bulk_g2s(stB + 2 * ABLK,        srcBh + (size_t)c * BBLK, BBLK, mbF + 8 * st);
                bulk_g2s(stB + 2 * ABLK + BBLK, srcBl + (size_t)c * BBLK, BBLK, mbF + 8 * st);
            }
        }
        return;
    }

    const int m0 = (warp >> 2) * 64;
    const int n0 = (warp & 3) * 48;
    FragOffs o;
    make_offs(o, m0, n0, lane);

    float acc[4][6][4];
    #pragma unroll
    for (int mi = 0; mi < 4; mi++)
        #pragma unroll
        for (int ni = 0; ni < 6; ni++)
            #pragma unroll
            for (int q = 0; q < 4; q++) acc[mi][ni][q] = 0.0f;

    for (int i = 0; i < 16; i++) {
        const int st = i & 1;
        mbar_wait(mbF + 8 * st, (uint32_t)((i >> 1) & 1));
        const uint32_t aHiB = sb + st * STAGE;
        chunk_mma(acc, o, aHiB, aHiB + ABLK, aHiB + 2 * ABLK, aHiB + 2 * ABLK + BBLK);
        if (lane == 0) mbar_arrive(mbE + 8 * st);
    }

    #pragma unroll
    for (int mi = 0; mi < 4; mi++) {
        const int r0 = mtile * MT + m0 + mi * 16 + (lane >> 2);
        #pragma unroll
        for (int ni = 0; ni < 6; ni++) {
            const int n = ntile * NT + n0 + ni * 8 + (lane & 3) * 2;
            #pragma unroll
            for (int h = 0; h < 2; h++) {
                const int row = r0 + h * 8;
                *(float2*)(g_cx + (size_t)row * NCOLS + n) =
                    make_float2(acc[mi][ni][2*h], acc[mi][ni][2*h+1]);
            }
        }
    }
}

// ---------------------------------------------------------------- GEMM step (pipelined)
// 256 threads = 8 compute warps (2x4, 64x48 tiles); warp-0/lane-0 doubles as producer.
// Fragment double-buffering across ks incl. chunk boundaries.
// NOTE: per-ks offset = base_offset XOR (ks*32) — swizzle mask (bits 4-6) and
// ks*32 (bits 5-6) overlap, so ADD is wrong; XOR is exact (colbase bit4 disjoint).
__global__ __launch_bounds__(256, 1)
void gemm_step(float* __restrict__ dout, int step) {
    extern __shared__ __align__(1024) char smem[];
    const uint32_t sb = s2u(smem);
    const int tid = threadIdx.x, warp = tid >> 5, lane = tid & 31;
    const int ntile = blockIdx.x, mtile = blockIdx.y;
    const int buf = step & 1;
    const bool last = (step == NSTEPS - 1);

    const char* srcAh = g_act_hi + (size_t)buf * ACT_BUF + (size_t)mtile * NKC * ABLK;
    const char* srcAl = g_act_lo + (size_t)buf * ACT_BUF + (size_t)mtile * NKC * ABLK;
    const char* srcBh = g_wt_hi + (size_t)ntile * NKC * BBLK;
    const char* srcBl = g_wt_lo + (size_t)ntile * NKC * BBLK;

    const uint32_t mbF = sb + SM_MBAR;
    const uint32_t mbE = sb + SM_MBAR + 16;
    float* sScale = (float*)(smem + SM_SSCALE);   // [128]
    float* sPart  = (float*)(smem + SM_SPART);    // [4][128]
    if (tid == 0) {
        mbar_init(mbF, 1); mbar_init(mbF + 8, 1);
        mbar_init(mbE, 8); mbar_init(mbE + 8, 8);
    }
    __syncthreads();

    // prologue: produce chunks 0,1 (warp0 lane0)
    if (tid == 0) {
        #pragma unroll
        for (int c = 0; c < NSTG; c++) {
            const int ck = 32 + c;                 // hid chunks first
            uint32_t stB = sb + c * STAGE;
            mbar_expect_tx(mbF + 8 * c, STAGE);
            bulk_g2s(stB,                   srcAh + (size_t)ck * ABLK, ABLK, mbF + 8 * c);
            bulk_g2s(stB + ABLK,            srcAl + (size_t)ck * ABLK, ABLK, mbF + 8 * c);
            bulk_g2s(stB + 2 * ABLK,        srcBh + (size_t)ck * BBLK, BBLK, mbF + 8 * c);
            bulk_g2s(stB + 2 * ABLK + BBLK, srcBl + (size_t)ck * BBLK, BBLK, mbF + 8 * c);
        }
    }
    // s_row from previous-step partials
    if (tid < MT) {
        const int grow = mtile * MT + tid;
        float ss = 0.0f;
        #pragma unroll
        for (int t = 0; t < NPART; t++) ss += g_part[t][grow];
        sScale[tid] = 1.0f / fmaxf(sqrtf(ss), EPS_N);
    }
    __syncthreads();

    const int m0 = (warp >> 2) * 64;
    const int n0 = (warp & 3) * 48;
    // base (ks=0) offsets; per-ks address = base XOR (ks*32)
    uint32_t aO[4], bO[3];
    #pragma unroll
    for (int mi = 0; mi < 4; mi++) {
        int row = m0 + mi * 16 + (lane & 15);
        aO[mi] = swz128((uint32_t)(row * ROWB + (lane >> 4) * 16));
    }
    #pragma unroll
    for (int nb = 0; nb < 3; nb++) {
        int grp = lane >> 3;
        int row = n0 + nb * 16 + ((grp & 2) << 2) + (lane & 7);
        bO[nb] = swz128((uint32_t)(row * ROWB + (grp & 1) * 16));
    }

    float acc[4][6][4];
    #pragma unroll
    for (int mi = 0; mi < 4; mi++)
        #pragma unroll
        for (int ni = 0; ni < 6; ni++)
            #pragma unroll
            for (int q = 0; q < 4; q++) acc[mi][ni][q] = 0.0f;

    // double-buffered fragments
    uint32_t ah[2][4][4], al[2][4][4], bh[2][6][2], bl[2][6][2];

#define LOADF(s, base, ksoff) do {                                            \
    const uint32_t _ah = (base), _al = (base) + ABLK;                         \
    const uint32_t _bh = (base) + 2 * ABLK, _bl = (base) + 2 * ABLK + BBLK;   \
    _Pragma("unroll")                                                         \
    for (int mi_ = 0; mi_ < 4; mi_++) {                                       \
        ldsm4(ah[s][mi_], (_ah + aO[mi_]) ^ (ksoff));                         \
        ldsm4(al[s][mi_], (_al + aO[mi_]) ^ (ksoff));                         \
    }                                                                         \
    _Pragma("unroll")                                                         \
    for (int nb_ = 0; nb_ < 3; nb_++) {                                       \
        uint32_t t_[4];                                                       \
        ldsm4(t_, (_bh + bO[nb_]) ^ (ksoff));                                 \
        bh[s][2*nb_][0] = t_[0]; bh[s][2*nb_][1] = t_[1];                     \
        bh[s][2*nb_+1][0] = t_[2]; bh[s][2*nb_+1][1] = t_[3];                 \
        ldsm4(t_, (_bl + bO[nb_]) ^ (ksoff));                                 \
        bl[s][2*nb_][0] = t_[0]; bl[s][2*nb_][1] = t_[1];                     \
        bl[s][2*nb_+1][0] = t_[2]; bl[s][2*nb_+1][1] = t_[3];                 \
    }                                                                         \
} while (0)

#define MMAF(s) do {                                                          \
    _Pragma("unroll")                                                         \
    for (int mi_ = 0; mi_ < 4; mi_++)                                         \
        _Pragma("unroll")                                                     \
        for (int ni_ = 0; ni_ < 6; ni_++) {                                   \
            mma16816(acc[mi_][ni_], ah[s][mi_], bh[s][ni_]);                  \
            mma16816(acc[mi_][ni_], ah[s][mi_], bl[s][ni_]);                  \
            mma16816(acc[mi_][ni_], al[s][mi_], bh[s][ni_]);                  \
        }                                                                     \
} while (0)

    // preload chunk 0 ks0 into slot 0
    mbar_wait(mbF, 0);
    LOADF(0, sb, 0);

    for (int i = 0; i < NITER; i++) {
        const int st = i & 1;
        const uint32_t base  = sb + st * STAGE;
        const uint32_t nbase = sb + ((i + 1) & 1) * STAGE;

        #pragma unroll
        for (int ks = 0; ks < 4; ks++) {
            const int p = ks & 1, q = p ^ 1;
            if (ks < 3) {
                LOADF(q, base, (ks + 1) * 32);
            } else if (i + 1 < NITER) {
                mbar_wait(mbF + 8 * ((i + 1) & 1), (uint32_t)(((i + 1) >> 1) & 1));
                LOADF(q, nbase, 0);
            }
            MMAF(p);
        }

        if (lane == 0) mbar_arrive(mbE + 8 * st);

        // inline producer: warp0 lane0 produces chunk i+2 into stage st
        if (tid == 0 && i + 2 < NITER) {
            mbar_wait(mbE + 8 * st, (uint32_t)((i >> 1) & 1));
            const int cN = i + 2;
            const int ck = (cN < 32) ? (32 + cN) : (cN - 16);
            uint32_t stB = sb + st * STAGE;
            mbar_expect_tx(mbF + 8 * st, STAGE);
            bulk_g2s(stB,                   srcAh + (size_t)ck * ABLK, ABLK, mbF + 8 * st);
            bulk_g2s(stB + ABLK,            srcAl + (size_t)ck * ABLK, ABLK, mbF + 8 * st);
            bulk_g2s(stB + 2 * ABLK,        srcBh + (size_t)ck * BBLK, BBLK, mbF + 8 * st);
            bulk_g2s(stB + 2 * ABLK + BBLK, srcBl + (size_t)ck * BBLK, BBLK, mbF + 8 * st);
        }

        if (i == 31) {   // all hid chunks done -> fold deferred norm scale
            #pragma unroll
            for (int mi = 0; mi < 4; mi++) {
                #pragma unroll
                for (int h = 0; h < 2; h++) {
                    const float s = sScale[m0 + mi * 16 + (lane >> 2) + h * 8];
                    #pragma unroll
                    for (int ni = 0; ni < 6; ni++) {
                        acc[mi][ni][2*h]   *= s;
                        acc[mi][ni][2*h+1] *= s;
                    }
                }
            }
        }
    }

    // epilogue: add C_x, relu, store, fused hid sum-of-squares partials
    char* dHi = g_act_hi + (size_t)(1 - buf) * ACT_BUF;
    char* dLo = g_act_lo + (size_t)(1 - buf) * ACT_BUF;
    float rowss[4][2];
    #pragma unroll
    for (int mi = 0; mi < 4; mi++) { rowss[mi][0] = 0.0f; rowss[mi][1] = 0.0f; }

    #pragma unroll
    for (int mi = 0; mi < 4; mi++) {
        const int r0 = mtile * MT + m0 + mi * 16 + (lane >> 2);
        #pragma unroll
        for (int ni = 0; ni < 6; ni++) {
            const int n = ntile * NT + n0 + ni * 8 + (lane & 3) * 2;
            const bool inHid = (n >= 1024);
            #pragma unroll
            for (int h = 0; h < 2; h++) {
                const int row = r0 + h * 8;
                float2 cx = *(const float2*)(g_cx + (size_t)row * NCOLS + n);
                float v0 = fmaxf(acc[mi][ni][2*h]   + cx.x, 0.0f);
                float v1 = fmaxf(acc[mi][ni][2*h+1] + cx.y, 0.0f);
                if (inHid) rowss[mi][h] += v0 * v0 + v1 * v1;
                if (last) {
                    *(float2*)(dout + (size_t)row * L_DIM + IN_DIM + n) = make_float2(v0, v1);
                } else {
                    uint32_t H, L;
                    split2(v0, v1, H, L);
                    size_t off = act_off(row, IN_DIM + n);
                    *(uint32_t*)(dHi + off) = H;
                    *(uint32_t*)(dLo + off) = L;
                }
            }
        }
    }

    if (ntile >= PART_T0) {
        #pragma unroll
        for (int mi = 0; mi < 4; mi++)
            #pragma unroll
            for (int h = 0; h < 2; h++) {
                float v = rowss[mi][h];
                v += __shfl_xor_sync(0xFFFFFFFFu, v, 1);
                v += __shfl_xor_sync(0xFFFFFFFFu, v, 2);
                if ((lane & 3) == 0)
                    sPart[(warp & 3) * MT + m0 + mi * 16 + (lane >> 2) + h * 8] = v;
            }
        __syncthreads();
        if (tid < MT) {
            float p = sPart[tid] + sPart[MT + tid] + sPart[2 * MT + tid] + sPart[3 * MT + tid];
            g_part[ntile - PART_T0][mtile * MT + tid] = p;
        }
    }
}

// ---------------------------------------------------------------- final normalize
__global__ __launch_bounds__(256)
void final_norm(float* __restrict__ dout) {
    const int row = blockIdx.x, t = threadIdx.x;
    float* hid = dout + (size_t)row * L_DIM + IN_DIM + OUT_DIM;
    float4 v0 = *(float4*)(hid + t * 8);
    float4 v1 = *(float4*)(hid + t * 8 + 4);
    float ss = v0.x*v0.x + v0.y*v0.y + v0.z*v0.z + v0.w*v0.w
             + v1.x*v1.x + v1.y*v1.y + v1.z*v1.z + v1.w*v1.w;
    __shared__ float red[8];
    __shared__ float s_scale;
    #pragma unroll
    for (int off = 16; off > 0; off >>= 1) ss += __shfl_xor_sync(0xFFFFFFFFu, ss, off);
    if ((t & 31) == 0) red[t >> 5] = ss;
    __syncthreads();
    if (t == 0) {
        float tot = 0.0f;
        #pragma unroll
        for (int w = 0; w < 8; w++) tot += red[w];
        s_scale = 1.0f / fmaxf(sqrtf(tot), EPS_N);
    }
    __syncthreads();
    const float sc = s_scale;
    v0.x *= sc; v0.y *= sc; v0.z *= sc; v0.w *= sc;
    v1.x *= sc; v1.y *= sc; v1.z *= sc; v1.w *= sc;
    *(float4*)(hid + t * 8)     = v0;
    *(float4*)(hid + t * 8 + 4) = v1;
}

// ---------------------------------------------------------------- launch
extern "C" void kernel_launch(void* const* d_in, const int* in_sizes, int n_in,
                              void* d_out, int out_size) {
    const float* x = (const float*)d_in[0];
    const float* W = (const float*)d_in[2];
    const float* A = (const float*)d_in[3];
    float* out = (float*)d_out;

    cudaFuncSetAttribute(gemm_cx,   cudaFuncAttributeMaxDynamicSharedMemorySize, SMEM_TOT);
    cudaFuncSetAttribute(gemm_step, cudaFuncAttributeMaxDynamicSharedMemorySize, SMEM_TOT);

    prep_w<<<dim3(L_DIM / 32, NCOLS / 32), dim3(32, 32)>>>(W, A);
    init_act<<<(B_DIM * 512) / 256, 256>>>(x, out);
    gemm_cx<<<dim3(NTILES, MTILES), 288, SMEM_TOT>>>(0);

    for (int s = 0; s < NSTEPS; s++) {
        gemm_step<<<dim3(NTILES, MTILES), 256, SMEM_TOT>>>(out, s);
    }
    final_norm<<<B_DIM, 256>>>(out);
}